// round 1
// baseline (speedup 1.0000x reference)
#include <cuda_runtime.h>
#include <cstdint>

#define N_NODES 100000
#define N_EDGES 1600000
#define N_TOT   1700000           // edges + self loops
#define NEG_SLOPE 0.2f
#define EPS 1e-16f

// ---------------- scratch (device globals; no allocation allowed) ----------
__device__ float g_h1[N_NODES * 64];    // layer-1 features  h = x@W1
__device__ float g_out1[N_NODES * 64];  // layer-1 aggregation output (+b1)
__device__ float g_h2[N_NODES * 8];     // layer-2 features (padded 7->8)
__device__ float g_as[N_NODES];         // alpha_src per node
__device__ float g_ad[N_NODES];         // alpha_dst per node
__device__ float g_max[N_NODES];        // segment max
__device__ float g_den[N_NODES];        // segment sum
__device__ float g_esc[N_TOT];          // per-edge score / exp score

// ---------------- helpers ----------------
__device__ __forceinline__ void atomicMaxF(float* addr, float v) {
    // standard monotone-bit-mapping float atomic max (valid incl. -inf init)
    if (v >= 0.f) atomicMax((int*)addr, __float_as_int(v));
    else          atomicMin((unsigned int*)addr, __float_as_uint(v));
}

__device__ __forceinline__ void red_add_v4(float* p, float a, float b, float c, float d) {
    asm volatile(
        "{ .reg .u64 pg; cvta.to.global.u64 pg, %0;\n\t"
        "red.global.add.v4.f32 [pg], {%1, %2, %3, %4}; }\n"
        :: "l"(p), "f"(a), "f"(b), "f"(c), "f"(d) : "memory");
}

// ---------------- K1: h1 = x @ W1 (100000x128 @ 128x64), also init out1=b1 --
// 64-row tile, 2 K-chunks of 64, 16x16 threads, 4x4 micro-tile.
__global__ void gemm1_kernel(const float* __restrict__ x,
                             const float* __restrict__ W1,
                             const float* __restrict__ b1) {
    __shared__ float xs[64 * 64];
    __shared__ float ws[64 * 64];
    const int t  = threadIdx.x;
    const int tx = t & 15, ty = t >> 4;
    const int rbase = blockIdx.x * 64;

    float acc[4][4];
#pragma unroll
    for (int i = 0; i < 4; i++)
#pragma unroll
        for (int j = 0; j < 4; j++) acc[i][j] = 0.f;

    for (int kc = 0; kc < 2; ++kc) {
#pragma unroll
        for (int i = 0; i < 16; ++i) {
            int idx = i * 256 + t;
            int r = idx >> 6, k = idx & 63;
            int gr = rbase + r;
            xs[idx] = (gr < N_NODES) ? x[gr * 128 + kc * 64 + k] : 0.f;
            ws[idx] = W1[(kc * 64 + r) * 64 + k];
        }
        __syncthreads();
#pragma unroll 8
        for (int kk = 0; kk < 64; ++kk) {
            float4 wv = *(const float4*)&ws[kk * 64 + tx * 4];
#pragma unroll
            for (int i = 0; i < 4; ++i) {
                float xv = xs[(ty * 4 + i) * 64 + kk];
                acc[i][0] += xv * wv.x;
                acc[i][1] += xv * wv.y;
                acc[i][2] += xv * wv.z;
                acc[i][3] += xv * wv.w;
            }
        }
        __syncthreads();
    }

    float4 b1v = *(const float4*)&b1[tx * 4];
#pragma unroll
    for (int i = 0; i < 4; ++i) {
        int gr = rbase + ty * 4 + i;
        if (gr < N_NODES) {
            float4 v;
            v.x = acc[i][0]; v.y = acc[i][1]; v.z = acc[i][2]; v.w = acc[i][3];
            *(float4*)&g_h1[gr * 64 + tx * 4]   = v;
            *(float4*)&g_out1[gr * 64 + tx * 4] = b1v;  // out1 starts at bias
        }
    }
}

// ---------------- K2: per-node alpha_src/alpha_dst, init max/den -----------
__global__ void alpha1_kernel(const float* __restrict__ a_src,
                              const float* __restrict__ a_dst) {
    int gt   = blockIdx.x * blockDim.x + threadIdx.x;
    int row  = gt >> 5;
    int lane = gt & 31;
    if (row >= N_NODES) return;
    float v0 = g_h1[row * 64 + lane];
    float v1 = g_h1[row * 64 + 32 + lane];
    float as = v0 * a_src[lane] + v1 * a_src[lane + 32];
    float ad = v0 * a_dst[lane] + v1 * a_dst[lane + 32];
#pragma unroll
    for (int off = 16; off > 0; off >>= 1) {
        as += __shfl_xor_sync(0xffffffffu, as, off);
        ad += __shfl_xor_sync(0xffffffffu, ad, off);
    }
    if (lane == 0) {
        g_as[row] = as;
        g_ad[row] = ad;
        g_max[row] = __int_as_float(0xff800000);  // -inf
        g_den[row] = 0.f;
    }
}

// ---------------- K3: per-edge score + segment max (shared by both layers) -
__global__ void edge_score_kernel(const int* __restrict__ ei,
                                  const float* __restrict__ ew) {
    int e = blockIdx.x * blockDim.x + threadIdx.x;
    if (e >= N_TOT) return;
    int s, d; float adj;
    if (e < N_EDGES) {
        s = ei[e]; d = ei[N_EDGES + e];
        adj = 1.f - 1.f / ew[e];
    } else {
        s = d = e - N_EDGES;   // self loop, weight 1 -> adj 0
        adj = 0.f;
    }
    float a = g_as[s] + g_ad[d];
    a = (a > 0.f) ? a : NEG_SLOPE * a;
    a += adj;
    g_esc[e] = a;
    atomicMaxF(&g_max[d], a);
}

// ---------------- K4: exp + segment sum ------------------------------------
__global__ void edge_exp_kernel(const int* __restrict__ ei) {
    int e = blockIdx.x * blockDim.x + threadIdx.x;
    if (e >= N_TOT) return;
    int d = (e < N_EDGES) ? ei[N_EDGES + e] : (e - N_EDGES);
    float ea = __expf(g_esc[e] - g_max[d]);
    g_esc[e] = ea;
    atomicAdd(&g_den[d], ea);
}

// ---------------- K5: layer-1 aggregation (64 feats, 16 lanes/edge) --------
__global__ void agg1_kernel(const int* __restrict__ ei) {
    int gt = blockIdx.x * blockDim.x + threadIdx.x;
    int e  = gt >> 4;
    if (e >= N_TOT) return;
    int li = gt & 15;
    int s, d;
    if (e < N_EDGES) { s = ei[e]; d = ei[N_EDGES + e]; }
    else             { s = d = e - N_EDGES; }
    float alpha = g_esc[e] / (g_den[d] + EPS);
    float4 h = *(const float4*)&g_h1[s * 64 + li * 4];
    red_add_v4(&g_out1[d * 64 + li * 4],
               h.x * alpha, h.y * alpha, h.z * alpha, h.w * alpha);
}

// ---------------- K6: relu + h2 = relu(out1)@W2, alpha2, reinit max/den ----
__global__ void layer2_kernel(const float* __restrict__ W2,
                              const float* __restrict__ a_src2,
                              const float* __restrict__ a_dst2) {
    __shared__ float w2s[448];
    if (threadIdx.x < 224) {
        w2s[threadIdx.x]       = W2[threadIdx.x];
        w2s[threadIdx.x + 224] = W2[threadIdx.x + 224];
    }
    __syncthreads();
    int gt   = blockIdx.x * blockDim.x + threadIdx.x;
    int row  = gt >> 5;
    int lane = gt & 31;
    if (row >= N_NODES) return;
    float v0 = fmaxf(g_out1[row * 64 + lane], 0.f);
    float v1 = fmaxf(g_out1[row * 64 + 32 + lane], 0.f);
    float p[7];
#pragma unroll
    for (int c = 0; c < 7; ++c)
        p[c] = v0 * w2s[lane * 7 + c] + v1 * w2s[(lane + 32) * 7 + c];
#pragma unroll
    for (int off = 16; off > 0; off >>= 1)
#pragma unroll
        for (int c = 0; c < 7; ++c)
            p[c] += __shfl_xor_sync(0xffffffffu, p[c], off);
    if (lane == 0) {
        float as = 0.f, ad = 0.f;
#pragma unroll
        for (int c = 0; c < 7; ++c) {
            as += p[c] * a_src2[c];
            ad += p[c] * a_dst2[c];
            g_h2[row * 8 + c] = p[c];
        }
        g_h2[row * 8 + 7] = 0.f;
        g_as[row] = as;
        g_ad[row] = ad;
        g_max[row] = __int_as_float(0xff800000);
        g_den[row] = 0.f;
    }
}

// ---------------- K7: out = b2 (broadcast init) ----------------------------
__global__ void init_out_kernel(float* __restrict__ out,
                                const float* __restrict__ b2) {
    int t = blockIdx.x * blockDim.x + threadIdx.x;
    if (t < N_NODES * 7) out[t] = b2[t % 7];
}

// ---------------- K8: layer-2 aggregation (7 feats, 8 lanes/edge) ----------
__global__ void agg2_kernel(const int* __restrict__ ei, float* __restrict__ out) {
    int gt = blockIdx.x * blockDim.x + threadIdx.x;
    int e  = gt >> 3;
    int c  = gt & 7;
    if (e >= N_TOT || c >= 7) return;
    int s, d;
    if (e < N_EDGES) { s = ei[e]; d = ei[N_EDGES + e]; }
    else             { s = d = e - N_EDGES; }
    float alpha = g_esc[e] / (g_den[d] + EPS);
    atomicAdd(&out[d * 7 + c], g_h2[s * 8 + c] * alpha);
}

// ---------------- launch ---------------------------------------------------
extern "C" void kernel_launch(void* const* d_in, const int* in_sizes, int n_in,
                              void* d_out, int out_size) {
    const float* x      = (const float*)d_in[0];
    const int*   ei     = (const int*)  d_in[1];
    const float* ew     = (const float*)d_in[2];
    const float* W1     = (const float*)d_in[3];
    const float* a_src1 = (const float*)d_in[4];
    const float* a_dst1 = (const float*)d_in[5];
    const float* b1     = (const float*)d_in[6];
    const float* W2     = (const float*)d_in[7];
    const float* a_src2 = (const float*)d_in[8];
    const float* a_dst2 = (const float*)d_in[9];
    const float* b2     = (const float*)d_in[10];
    float* out = (float*)d_out;

    // ---- layer 1 ----
    gemm1_kernel<<<(N_NODES + 63) / 64, 256>>>(x, W1, b1);
    alpha1_kernel<<<(N_NODES * 32 + 255) / 256, 256>>>(a_src1, a_dst1);
    edge_score_kernel<<<(N_TOT + 255) / 256, 256>>>(ei, ew);
    edge_exp_kernel<<<(N_TOT + 255) / 256, 256>>>(ei);
    agg1_kernel<<<(N_TOT * 16 + 255) / 256, 256>>>(ei);

    // ---- layer 2 ----
    layer2_kernel<<<(N_NODES * 32 + 255) / 256, 256>>>(W2, a_src2, a_dst2);
    edge_score_kernel<<<(N_TOT + 255) / 256, 256>>>(ei, ew);
    edge_exp_kernel<<<(N_TOT + 255) / 256, 256>>>(ei);
    init_out_kernel<<<(N_NODES * 7 + 255) / 256, 256>>>(out, b2);
    agg2_kernel<<<(N_TOT * 8 + 255) / 256, 256>>>(ei, out);
}

// round 2
// speedup vs baseline: 1.2010x; 1.2010x over previous
#include <cuda_runtime.h>
#include <cstdint>

#define N_NODES 100000
#define N_EDGES 1600000
#define N_TOT   1700000           // edges + self loops
#define NEG_SLOPE 0.2f
#define EPS 1e-16f

// ---------------- scratch (device globals; no allocation allowed) ----------
__device__ float g_h1[N_NODES * 64];    // layer-1 features  h = x@W1
__device__ float g_out1[N_NODES * 64];  // layer-1 aggregation output (+b1)
__device__ float g_h2[N_NODES * 8];     // layer-2 features (padded 7->8)
__device__ float g_as[N_NODES];         // alpha_src per node
__device__ float g_ad[N_NODES];         // alpha_dst per node
__device__ float g_den[N_NODES];        // segment sum -> reciprocal
__device__ float g_esc[N_TOT];          // per-edge exp score

// ---------------- helpers ----------------
__device__ __forceinline__ void red_add_v4(float* p, float a, float b, float c, float d) {
    asm volatile(
        "{ .reg .u64 pg; cvta.to.global.u64 pg, %0;\n\t"
        "red.global.add.v4.f32 [pg], {%1, %2, %3, %4}; }\n"
        :: "l"(p), "f"(a), "f"(b), "f"(c), "f"(d) : "memory");
}

// ---------------- K1: h1 = x @ W1, fused alpha_src/alpha_dst + inits -------
// 64-row tile, 2 K-chunks of 64, 16x16 threads, 4x4 micro-tile.
__global__ void gemm1_kernel(const float* __restrict__ x,
                             const float* __restrict__ W1,
                             const float* __restrict__ b1,
                             const float* __restrict__ a_src,
                             const float* __restrict__ a_dst) {
    __shared__ float xs[64 * 64];
    __shared__ float ws[64 * 64];
    const int t  = threadIdx.x;
    const int tx = t & 15, ty = t >> 4;
    const int rbase = blockIdx.x * 64;

    float acc[4][4];
#pragma unroll
    for (int i = 0; i < 4; i++)
#pragma unroll
        for (int j = 0; j < 4; j++) acc[i][j] = 0.f;

    for (int kc = 0; kc < 2; ++kc) {
#pragma unroll
        for (int i = 0; i < 16; ++i) {
            int idx = i * 256 + t;
            int r = idx >> 6, k = idx & 63;
            int gr = rbase + r;
            xs[idx] = (gr < N_NODES) ? x[gr * 128 + kc * 64 + k] : 0.f;
            ws[idx] = W1[(kc * 64 + r) * 64 + k];
        }
        __syncthreads();
#pragma unroll 8
        for (int kk = 0; kk < 64; ++kk) {
            float4 wv = *(const float4*)&ws[kk * 64 + tx * 4];
#pragma unroll
            for (int i = 0; i < 4; ++i) {
                float xv = xs[(ty * 4 + i) * 64 + kk];
                acc[i][0] += xv * wv.x;
                acc[i][1] += xv * wv.y;
                acc[i][2] += xv * wv.z;
                acc[i][3] += xv * wv.w;
            }
        }
        __syncthreads();
    }

    float4 b1v = *(const float4*)&b1[tx * 4];
    float4 asv = *(const float4*)&a_src[tx * 4];
    float4 adv = *(const float4*)&a_dst[tx * 4];
#pragma unroll
    for (int i = 0; i < 4; ++i) {
        int gr = rbase + ty * 4 + i;
        if (gr < N_NODES) {
            float4 v;
            v.x = acc[i][0]; v.y = acc[i][1]; v.z = acc[i][2]; v.w = acc[i][3];
            *(float4*)&g_h1[gr * 64 + tx * 4]   = v;
            *(float4*)&g_out1[gr * 64 + tx * 4] = b1v;  // out1 starts at bias
        }
        // fused partial dot products for alpha_src / alpha_dst
        float pas = acc[i][0] * asv.x + acc[i][1] * asv.y +
                    acc[i][2] * asv.z + acc[i][3] * asv.w;
        float pad = acc[i][0] * adv.x + acc[i][1] * adv.y +
                    acc[i][2] * adv.z + acc[i][3] * adv.w;
#pragma unroll
        for (int off = 8; off > 0; off >>= 1) {
            pas += __shfl_xor_sync(0xffffffffu, pas, off);
            pad += __shfl_xor_sync(0xffffffffu, pad, off);
        }
        if (tx == 0 && gr < N_NODES) {
            g_as[gr]  = pas;
            g_ad[gr]  = pad;
            g_den[gr] = 0.f;
        }
    }
}

// ---------------- K2: fused per-edge score + exp + segment sum -------------
// (no max subtraction: softmax is shift-invariant; scores bounded ~[-2, +8])
__global__ void edge_fused_kernel(const int* __restrict__ ei,
                                  const float* __restrict__ ew) {
    int e = blockIdx.x * blockDim.x + threadIdx.x;
    if (e >= N_TOT) return;
    int s, d; float adj;
    if (e < N_EDGES) {
        s = ei[e]; d = ei[N_EDGES + e];
        adj = 1.f - 1.f / ew[e];
    } else {
        s = d = e - N_EDGES;   // self loop, weight 1 -> adj 0
        adj = 0.f;
    }
    float a = g_as[s] + g_ad[d];
    a = (a > 0.f) ? a : NEG_SLOPE * a;
    a += adj;
    float ea = __expf(a);
    g_esc[e] = ea;
    atomicAdd(&g_den[d], ea);
}

// ---------------- K3: den -> 1/(den+eps) -----------------------------------
__global__ void invden_kernel() {
    int i = blockIdx.x * blockDim.x + threadIdx.x;
    if (i < N_NODES) g_den[i] = 1.f / (g_den[i] + EPS);
}

// ---------------- K4: layer-1 aggregation (64 feats, 16 lanes/edge) --------
__global__ void agg1_kernel(const int* __restrict__ ei) {
    int gt = blockIdx.x * blockDim.x + threadIdx.x;
    int e  = gt >> 4;
    if (e >= N_TOT) return;
    int li = gt & 15;
    int s, d;
    if (e < N_EDGES) { s = ei[e]; d = ei[N_EDGES + e]; }
    else             { s = d = e - N_EDGES; }
    float alpha = g_esc[e] * g_den[d];
    float4 h = *(const float4*)&g_h1[s * 64 + li * 4];
    red_add_v4(&g_out1[d * 64 + li * 4],
               h.x * alpha, h.y * alpha, h.z * alpha, h.w * alpha);
}

// ---------------- K5: relu + h2 = relu(out1)@W2, alpha2, reinit den --------
__global__ void layer2_kernel(const float* __restrict__ W2,
                              const float* __restrict__ a_src2,
                              const float* __restrict__ a_dst2) {
    __shared__ float w2s[448];
    if (threadIdx.x < 224) {
        w2s[threadIdx.x]       = W2[threadIdx.x];
        w2s[threadIdx.x + 224] = W2[threadIdx.x + 224];
    }
    __syncthreads();
    int gt   = blockIdx.x * blockDim.x + threadIdx.x;
    int row  = gt >> 5;
    int lane = gt & 31;
    if (row >= N_NODES) return;
    float v0 = fmaxf(g_out1[row * 64 + lane], 0.f);
    float v1 = fmaxf(g_out1[row * 64 + 32 + lane], 0.f);
    float p[7];
#pragma unroll
    for (int c = 0; c < 7; ++c)
        p[c] = v0 * w2s[lane * 7 + c] + v1 * w2s[(lane + 32) * 7 + c];
#pragma unroll
    for (int off = 16; off > 0; off >>= 1)
#pragma unroll
        for (int c = 0; c < 7; ++c)
            p[c] += __shfl_xor_sync(0xffffffffu, p[c], off);
    if (lane == 0) {
        float as = 0.f, ad = 0.f;
#pragma unroll
        for (int c = 0; c < 7; ++c) {
            as += p[c] * a_src2[c];
            ad += p[c] * a_dst2[c];
            g_h2[row * 8 + c] = p[c];
        }
        g_h2[row * 8 + 7] = 0.f;
        g_as[row]  = as;
        g_ad[row]  = ad;
        g_den[row] = 0.f;
    }
}

// ---------------- K6: out = b2 (broadcast init) ----------------------------
__global__ void init_out_kernel(float* __restrict__ out,
                                const float* __restrict__ b2) {
    int t = blockIdx.x * blockDim.x + threadIdx.x;
    if (t < N_NODES * 7) out[t] = b2[t % 7];
}

// ---------------- K7: layer-2 aggregation (7 feats, 8 lanes/edge) ----------
__global__ void agg2_kernel(const int* __restrict__ ei, float* __restrict__ out) {
    int gt = blockIdx.x * blockDim.x + threadIdx.x;
    int e  = gt >> 3;
    int c  = gt & 7;
    if (e >= N_TOT || c >= 7) return;
    int s, d;
    if (e < N_EDGES) { s = ei[e]; d = ei[N_EDGES + e]; }
    else             { s = d = e - N_EDGES; }
    float alpha = g_esc[e] * g_den[d];
    atomicAdd(&out[d * 7 + c], g_h2[s * 8 + c] * alpha);
}

// ---------------- launch ---------------------------------------------------
extern "C" void kernel_launch(void* const* d_in, const int* in_sizes, int n_in,
                              void* d_out, int out_size) {
    const float* x      = (const float*)d_in[0];
    const int*   ei     = (const int*)  d_in[1];
    const float* ew     = (const float*)d_in[2];
    const float* W1     = (const float*)d_in[3];
    const float* a_src1 = (const float*)d_in[4];
    const float* a_dst1 = (const float*)d_in[5];
    const float* b1     = (const float*)d_in[6];
    const float* W2     = (const float*)d_in[7];
    const float* a_src2 = (const float*)d_in[8];
    const float* a_dst2 = (const float*)d_in[9];
    const float* b2     = (const float*)d_in[10];
    float* out = (float*)d_out;

    // ---- layer 1 ----
    gemm1_kernel<<<(N_NODES + 63) / 64, 256>>>(x, W1, b1, a_src1, a_dst1);
    edge_fused_kernel<<<(N_TOT + 255) / 256, 256>>>(ei, ew);
    invden_kernel<<<(N_NODES + 255) / 256, 256>>>();
    agg1_kernel<<<(N_TOT * 16 + 255) / 256, 256>>>(ei);

    // ---- layer 2 ----
    layer2_kernel<<<(N_NODES * 32 + 255) / 256, 256>>>(W2, a_src2, a_dst2);
    edge_fused_kernel<<<(N_TOT + 255) / 256, 256>>>(ei, ew);
    invden_kernel<<<(N_NODES + 255) / 256, 256>>>();
    init_out_kernel<<<(N_NODES * 7 + 255) / 256, 256>>>(out, b2);
    agg2_kernel<<<(N_TOT * 8 + 255) / 256, 256>>>(ei, out);
}

// round 3
// speedup vs baseline: 1.6080x; 1.3389x over previous
#include <cuda_runtime.h>
#include <cstdint>

#define N_NODES 100000
#define N_EDGES 1600000
#define N_TOT   1700000           // edges + self loops
#define NEG_SLOPE 0.2f
#define EPS 1e-16f
#define SCAN_B 1024
#define NSCAN ((N_NODES + SCAN_B - 1) / SCAN_B)   // 98

// ---------------- scratch (device globals; no allocation allowed) ----------
__device__ float g_h1[N_NODES * 64];    // layer-1 features  h = x@W1
__device__ float g_h2[N_NODES * 8];     // layer-2 features (padded 7->8)
__device__ float g_as[N_NODES];         // layer-1 alpha_src per node
__device__ float g_ad[N_NODES];         // layer-1 alpha_dst per node
__device__ float g_as2[N_NODES];        // layer-2 alpha_src per node
__device__ float g_ad2[N_NODES];        // layer-2 alpha_dst per node
__device__ int   g_deg[N_NODES];        // in-degree histogram
__device__ int   g_off[N_NODES + 1];    // CSR row offsets (by dst)
__device__ int   g_cur[N_NODES];        // scatter cursors
__device__ int   g_bsum[NSCAN];         // scan block sums
__device__ int2  g_es[N_TOT];           // CSR payload: (src, adj bits)

// ---------------- K1: h1 = x @ W1, fused alpha_src/alpha_dst, zero deg -----
__global__ void gemm1_kernel(const float* __restrict__ x,
                             const float* __restrict__ W1,
                             const float* __restrict__ a_src,
                             const float* __restrict__ a_dst) {
    __shared__ float xs[64 * 64];
    __shared__ float ws[64 * 64];
    const int t  = threadIdx.x;
    const int tx = t & 15, ty = t >> 4;
    const int rbase = blockIdx.x * 64;

    // zero degree histogram for the CSR build (runs before hist kernel)
    if (t < 64) {
        int gr = rbase + t;
        if (gr < N_NODES) g_deg[gr] = 0;
    }

    float acc[4][4];
#pragma unroll
    for (int i = 0; i < 4; i++)
#pragma unroll
        for (int j = 0; j < 4; j++) acc[i][j] = 0.f;

    for (int kc = 0; kc < 2; ++kc) {
#pragma unroll
        for (int i = 0; i < 16; ++i) {
            int idx = i * 256 + t;
            int r = idx >> 6, k = idx & 63;
            int gr = rbase + r;
            xs[idx] = (gr < N_NODES) ? x[gr * 128 + kc * 64 + k] : 0.f;
            ws[idx] = W1[(kc * 64 + r) * 64 + k];
        }
        __syncthreads();
#pragma unroll 8
        for (int kk = 0; kk < 64; ++kk) {
            float4 wv = *(const float4*)&ws[kk * 64 + tx * 4];
#pragma unroll
            for (int i = 0; i < 4; ++i) {
                float xv = xs[(ty * 4 + i) * 64 + kk];
                acc[i][0] += xv * wv.x;
                acc[i][1] += xv * wv.y;
                acc[i][2] += xv * wv.z;
                acc[i][3] += xv * wv.w;
            }
        }
        __syncthreads();
    }

    float4 asv = *(const float4*)&a_src[tx * 4];
    float4 adv = *(const float4*)&a_dst[tx * 4];
#pragma unroll
    for (int i = 0; i < 4; ++i) {
        int gr = rbase + ty * 4 + i;
        if (gr < N_NODES) {
            float4 v;
            v.x = acc[i][0]; v.y = acc[i][1]; v.z = acc[i][2]; v.w = acc[i][3];
            *(float4*)&g_h1[gr * 64 + tx * 4] = v;
        }
        float pas = acc[i][0] * asv.x + acc[i][1] * asv.y +
                    acc[i][2] * asv.z + acc[i][3] * asv.w;
        float pad = acc[i][0] * adv.x + acc[i][1] * adv.y +
                    acc[i][2] * adv.z + acc[i][3] * adv.w;
#pragma unroll
        for (int off = 8; off > 0; off >>= 1) {
            pas += __shfl_xor_sync(0xffffffffu, pas, off);
            pad += __shfl_xor_sync(0xffffffffu, pad, off);
        }
        if (tx == 0 && gr < N_NODES) {
            g_as[gr] = pas;
            g_ad[gr] = pad;
        }
    }
}

// ---------------- CSR build --------------------------------------------------
__global__ void hist_kernel(const int* __restrict__ ei) {
    int e = blockIdx.x * blockDim.x + threadIdx.x;
    if (e >= N_TOT) return;
    int d = (e < N_EDGES) ? ei[N_EDGES + e] : (e - N_EDGES);
    atomicAdd(&g_deg[d], 1);
}

__global__ void scanA_kernel() {
    __shared__ int sh[256];
    int tid  = threadIdx.x;
    int base = blockIdx.x * SCAN_B + tid * 4;
    int v[4];
#pragma unroll
    for (int k = 0; k < 4; ++k)
        v[k] = (base + k < N_NODES) ? g_deg[base + k] : 0;
    int local = v[0] + v[1] + v[2] + v[3];
    sh[tid] = local;
    __syncthreads();
    for (int off = 1; off < 256; off <<= 1) {
        int t2 = (tid >= off) ? sh[tid - off] : 0;
        __syncthreads();
        sh[tid] += t2;
        __syncthreads();
    }
    int incl = sh[tid];
    if (tid == 255) g_bsum[blockIdx.x] = incl;
    int run = incl - local;
#pragma unroll
    for (int k = 0; k < 4; ++k) {
        if (base + k < N_NODES) g_off[base + k] = run;
        run += v[k];
    }
}

__global__ void scanB_kernel() {
    __shared__ int sh[128];
    int tid = threadIdx.x;
    int v = (tid < NSCAN) ? g_bsum[tid] : 0;
    sh[tid] = v;
    __syncthreads();
    for (int off = 1; off < 128; off <<= 1) {
        int t2 = (tid >= off) ? sh[tid - off] : 0;
        __syncthreads();
        sh[tid] += t2;
        __syncthreads();
    }
    if (tid < NSCAN) g_bsum[tid] = sh[tid] - v;   // exclusive
}

__global__ void scanC_kernel() {
    int i = blockIdx.x * blockDim.x + threadIdx.x;
    if (i < N_NODES) {
        int o = g_off[i] + g_bsum[i >> 10];
        g_off[i] = o;
        g_cur[i] = o;
    }
    if (i == 0) g_off[N_NODES] = N_TOT;
}

__global__ void scatter_kernel(const int* __restrict__ ei,
                               const float* __restrict__ ew) {
    int e = blockIdx.x * blockDim.x + threadIdx.x;
    if (e >= N_TOT) return;
    int s, d; float adj;
    if (e < N_EDGES) {
        s = ei[e]; d = ei[N_EDGES + e];
        adj = 1.f - 1.f / ew[e];
    } else {
        s = d = e - N_EDGES;
        adj = 0.f;
    }
    int pos = atomicAdd(&g_cur[d], 1);
    g_es[pos] = make_int2(s, __float_as_int(adj));
}

// ---------------- K2: fused layer-1 softmax+aggregate + layer-2 features ----
// One warp per dst node, 2 features per lane. After gathering out1 in regs,
// applies bias+relu and computes h2 = relu(out1)@W2 and alpha2 in-place.
__global__ void agg1_csr_kernel(const float* __restrict__ b1,
                                const float* __restrict__ W2,
                                const float* __restrict__ a_src2,
                                const float* __restrict__ a_dst2) {
    __shared__ float w2s[448];
    __shared__ float as2s[8], ad2s[8];
    int tid = threadIdx.x;
    if (tid < 224) { w2s[tid] = W2[tid]; w2s[tid + 224] = W2[tid + 224]; }
    if (tid < 7)   { as2s[tid] = a_src2[tid]; ad2s[tid] = a_dst2[tid]; }
    __syncthreads();

    int d    = (blockIdx.x * blockDim.x + tid) >> 5;
    int lane = tid & 31;
    if (d >= N_NODES) return;

    float ad_d = g_ad[d];
    int j = g_off[d], end = g_off[d + 1];
    float den = 0.f, a0 = 0.f, a1 = 0.f;
    const float2* h1p = (const float2*)g_h1;

    for (; j + 1 < end; j += 2) {
        int2 e0 = g_es[j];
        int2 e1 = g_es[j + 1];
        float sa0 = g_as[e0.x];
        float sa1 = g_as[e1.x];
        float2 h0 = h1p[e0.x * 32 + lane];
        float2 h1v = h1p[e1.x * 32 + lane];
        float x0 = sa0 + ad_d; x0 = (x0 > 0.f) ? x0 : NEG_SLOPE * x0;
        float x1 = sa1 + ad_d; x1 = (x1 > 0.f) ? x1 : NEG_SLOPE * x1;
        float ea0 = __expf(x0 + __int_as_float(e0.y));
        float ea1 = __expf(x1 + __int_as_float(e1.y));
        den += ea0 + ea1;
        a0 += ea0 * h0.x + ea1 * h1v.x;
        a1 += ea0 * h0.y + ea1 * h1v.y;
    }
    if (j < end) {
        int2 e0 = g_es[j];
        float sa0 = g_as[e0.x];
        float2 h0 = h1p[e0.x * 32 + lane];
        float x0 = sa0 + ad_d; x0 = (x0 > 0.f) ? x0 : NEG_SLOPE * x0;
        float ea0 = __expf(x0 + __int_as_float(e0.y));
        den += ea0;
        a0 += ea0 * h0.x;
        a1 += ea0 * h0.y;
    }

    float inv = 1.f / (den + EPS);
    // out1 features (bias + relu), 2 per lane
    float f0 = fmaxf(fmaf(a0, inv, b1[lane * 2]),     0.f);
    float f1 = fmaxf(fmaf(a1, inv, b1[lane * 2 + 1]), 0.f);

    // GEMM2: p[c] = sum over 64 feats of f * W2[feat][c]
    float p[7];
#pragma unroll
    for (int c = 0; c < 7; ++c)
        p[c] = f0 * w2s[(lane * 2) * 7 + c] + f1 * w2s[(lane * 2 + 1) * 7 + c];
#pragma unroll
    for (int off = 16; off > 0; off >>= 1)
#pragma unroll
        for (int c = 0; c < 7; ++c)
            p[c] += __shfl_xor_sync(0xffffffffu, p[c], off);

    if (lane == 0) {
        float4 v0 = make_float4(p[0], p[1], p[2], p[3]);
        float4 v1 = make_float4(p[4], p[5], p[6], 0.f);
        *(float4*)&g_h2[d * 8]     = v0;
        *(float4*)&g_h2[d * 8 + 4] = v1;
        float s2 = 0.f, t2 = 0.f;
#pragma unroll
        for (int c = 0; c < 7; ++c) {
            s2 += p[c] * as2s[c];
            t2 += p[c] * ad2s[c];
        }
        g_as2[d] = s2;
        g_ad2[d] = t2;
    }
}

// ---------------- K3: fused layer-2 softmax+aggregate (8 lanes / dst) -------
__global__ void agg2_csr_kernel(float* __restrict__ out,
                                const float* __restrict__ b2) {
    int gt = blockIdx.x * blockDim.x + threadIdx.x;
    int d  = gt >> 3;
    int c  = gt & 7;
    if (d >= N_NODES) return;

    float ad_d = g_ad2[d];
    int j = g_off[d], end = g_off[d + 1];
    float den = 0.f, acc = 0.f;
    for (; j < end; ++j) {
        int2 e0 = g_es[j];
        float a = g_as2[e0.x] + ad_d;
        a = (a > 0.f) ? a : NEG_SLOPE * a;
        float ea = __expf(a + __int_as_float(e0.y));
        den += ea;
        acc += ea * g_h2[e0.x * 8 + c];
    }
    if (c < 7)
        out[d * 7 + c] = fmaf(acc, 1.f / (den + EPS), b2[c]);
}

// ---------------- launch ---------------------------------------------------
extern "C" void kernel_launch(void* const* d_in, const int* in_sizes, int n_in,
                              void* d_out, int out_size) {
    const float* x      = (const float*)d_in[0];
    const int*   ei     = (const int*)  d_in[1];
    const float* ew     = (const float*)d_in[2];
    const float* W1     = (const float*)d_in[3];
    const float* a_src1 = (const float*)d_in[4];
    const float* a_dst1 = (const float*)d_in[5];
    const float* b1     = (const float*)d_in[6];
    const float* W2     = (const float*)d_in[7];
    const float* a_src2 = (const float*)d_in[8];
    const float* a_dst2 = (const float*)d_in[9];
    const float* b2     = (const float*)d_in[10];
    float* out = (float*)d_out;

    // GEMM1 + alpha1 (also zeroes the degree histogram)
    gemm1_kernel<<<(N_NODES + 63) / 64, 256>>>(x, W1, a_src1, a_dst1);

    // CSR build (by destination), reused by both layers
    hist_kernel<<<(N_TOT + 255) / 256, 256>>>(ei);
    scanA_kernel<<<NSCAN, 256>>>();
    scanB_kernel<<<1, 128>>>();
    scanC_kernel<<<(N_NODES + 255) / 256, 256>>>();
    scatter_kernel<<<(N_TOT + 255) / 256, 256>>>(ei, ew);

    // layer 1 aggregate + layer 2 features, then layer 2 aggregate
    agg1_csr_kernel<<<(N_NODES * 32 + 255) / 256, 256>>>(b1, W2, a_src2, a_dst2);
    agg2_csr_kernel<<<(N_NODES * 8 + 255) / 256, 256>>>(out, b2);
}

// round 4
// speedup vs baseline: 1.7455x; 1.0855x over previous
#include <cuda_runtime.h>
#include <cuda_fp16.h>
#include <cstdint>

#define N_NODES 100000
#define N_EDGES 1600000
#define N_TOT   1700000           // edges + self loops
#define NEG_SLOPE 0.2f
#define EPS 1e-16f
#define SCAN_B 1024
#define NSCAN ((N_NODES + SCAN_B - 1) / SCAN_B)   // 98

// ---------------- scratch (device globals; no allocation allowed) ----------
__device__ __half2 g_h1h[N_NODES * 32];  // layer-1 features (fp16, gather-only)
__device__ float g_h2[N_NODES * 8];      // layer-2 features (padded 7->8)
__device__ float g_as[N_NODES];          // layer-1 alpha_src per node
__device__ float g_ad[N_NODES];          // layer-1 alpha_dst per node
__device__ float g_as2[N_NODES];         // layer-2 alpha_src per node
__device__ float g_ad2[N_NODES];         // layer-2 alpha_dst per node
__device__ int   g_deg[N_NODES];         // in-degree histogram
__device__ int   g_off[N_NODES + 1];     // CSR row offsets (by dst)
__device__ int   g_cur[N_NODES];         // scatter cursors
__device__ int   g_bsum[NSCAN];          // scan block sums
__device__ int2  g_es[N_TOT];            // CSR payload: (src, adj bits)

// ---------------- K1: h1 = x @ W1 (fp16 store), fused alphas ---------------
__global__ void gemm1_kernel(const float* __restrict__ x,
                             const float* __restrict__ W1,
                             const float* __restrict__ a_src,
                             const float* __restrict__ a_dst) {
    __shared__ float xs[64 * 64];
    __shared__ float ws[64 * 64];
    const int t  = threadIdx.x;
    const int tx = t & 15, ty = t >> 4;
    const int rbase = blockIdx.x * 64;

    float acc[4][4];
#pragma unroll
    for (int i = 0; i < 4; i++)
#pragma unroll
        for (int j = 0; j < 4; j++) acc[i][j] = 0.f;

    for (int kc = 0; kc < 2; ++kc) {
#pragma unroll
        for (int i = 0; i < 16; ++i) {
            int idx = i * 256 + t;
            int r = idx >> 6, k = idx & 63;
            int gr = rbase + r;
            xs[idx] = (gr < N_NODES) ? x[gr * 128 + kc * 64 + k] : 0.f;
            ws[idx] = W1[(kc * 64 + r) * 64 + k];
        }
        __syncthreads();
#pragma unroll 8
        for (int kk = 0; kk < 64; ++kk) {
            float4 wv = *(const float4*)&ws[kk * 64 + tx * 4];
#pragma unroll
            for (int i = 0; i < 4; ++i) {
                float xv = xs[(ty * 4 + i) * 64 + kk];
                acc[i][0] += xv * wv.x;
                acc[i][1] += xv * wv.y;
                acc[i][2] += xv * wv.z;
                acc[i][3] += xv * wv.w;
            }
        }
        __syncthreads();
    }

    float4 asv = *(const float4*)&a_src[tx * 4];
    float4 adv = *(const float4*)&a_dst[tx * 4];
#pragma unroll
    for (int i = 0; i < 4; ++i) {
        int gr = rbase + ty * 4 + i;
        if (gr < N_NODES) {
            __half2 hA = __floats2half2_rn(acc[i][0], acc[i][1]);
            __half2 hB = __floats2half2_rn(acc[i][2], acc[i][3]);
            uint2 pk;
            pk.x = reinterpret_cast<unsigned int&>(hA);
            pk.y = reinterpret_cast<unsigned int&>(hB);
            *(uint2*)&g_h1h[gr * 32 + tx * 2] = pk;
        }
        float pas = acc[i][0] * asv.x + acc[i][1] * asv.y +
                    acc[i][2] * asv.z + acc[i][3] * asv.w;
        float pad = acc[i][0] * adv.x + acc[i][1] * adv.y +
                    acc[i][2] * adv.z + acc[i][3] * adv.w;
#pragma unroll
        for (int off = 8; off > 0; off >>= 1) {
            pas += __shfl_xor_sync(0xffffffffu, pas, off);
            pad += __shfl_xor_sync(0xffffffffu, pad, off);
        }
        if (tx == 0 && gr < N_NODES) {
            g_as[gr] = pas;
            g_ad[gr] = pad;
        }
    }
}

// ---------------- CSR build (side stream, overlapped with gemm1) -----------
__global__ void zero_deg_kernel() {
    int i = blockIdx.x * blockDim.x + threadIdx.x;
    if (i < N_NODES) g_deg[i] = 0;
}

__global__ void hist_kernel(const int* __restrict__ ei) {
    int e = blockIdx.x * blockDim.x + threadIdx.x;
    if (e >= N_TOT) return;
    int d = (e < N_EDGES) ? ei[N_EDGES + e] : (e - N_EDGES);
    atomicAdd(&g_deg[d], 1);
}

__global__ void scanA_kernel() {
    __shared__ int sh[256];
    int tid  = threadIdx.x;
    int base = blockIdx.x * SCAN_B + tid * 4;
    int v[4];
#pragma unroll
    for (int k = 0; k < 4; ++k)
        v[k] = (base + k < N_NODES) ? g_deg[base + k] : 0;
    int local = v[0] + v[1] + v[2] + v[3];
    sh[tid] = local;
    __syncthreads();
    for (int off = 1; off < 256; off <<= 1) {
        int t2 = (tid >= off) ? sh[tid - off] : 0;
        __syncthreads();
        sh[tid] += t2;
        __syncthreads();
    }
    int incl = sh[tid];
    if (tid == 255) g_bsum[blockIdx.x] = incl;
    int run = incl - local;
#pragma unroll
    for (int k = 0; k < 4; ++k) {
        if (base + k < N_NODES) g_off[base + k] = run;
        run += v[k];
    }
}

// scanC folds the (tiny) 98-entry block-sum scan in redundantly per block.
__global__ void scanC_kernel() {
    __shared__ int sh[128];
    __shared__ int orig[128];
    int tid = threadIdx.x;
    if (tid < 128) {
        int v = (tid < NSCAN) ? g_bsum[tid] : 0;
        orig[tid] = v;
        sh[tid] = v;
    }
    __syncthreads();
    for (int off = 1; off < 128; off <<= 1) {
        int t2 = (tid >= off && tid < 128) ? sh[tid - off] : 0;
        __syncthreads();
        if (tid < 128) sh[tid] += t2;
        __syncthreads();
    }
    int i = blockIdx.x * blockDim.x + tid;
    if (i < N_NODES) {
        int blk = i >> 10;
        int o = g_off[i] + (sh[blk] - orig[blk]);   // + exclusive block prefix
        g_off[i] = o;
        g_cur[i] = o;
    }
    if (i == 0) g_off[N_NODES] = N_TOT;
}

__global__ void scatter_kernel(const int* __restrict__ ei,
                               const float* __restrict__ ew) {
    int e = blockIdx.x * blockDim.x + threadIdx.x;
    if (e >= N_TOT) return;
    int s, d; float adj;
    if (e < N_EDGES) {
        s = ei[e]; d = ei[N_EDGES + e];
        adj = 1.f - 1.f / ew[e];
    } else {
        s = d = e - N_EDGES;
        adj = 0.f;
    }
    int pos = atomicAdd(&g_cur[d], 1);
    g_es[pos] = make_int2(s, __float_as_int(adj));
}

// ---------------- K2: fused layer-1 softmax+aggregate + layer-2 features ----
// One warp per dst node, 2 features per lane (one half2 gather per edge).
__global__ void agg1_csr_kernel(const float* __restrict__ b1,
                                const float* __restrict__ W2,
                                const float* __restrict__ a_src2,
                                const float* __restrict__ a_dst2) {
    __shared__ float w2s[448];
    __shared__ float as2s[8], ad2s[8];
    int tid = threadIdx.x;
    if (tid < 224) { w2s[tid] = W2[tid]; w2s[tid + 224] = W2[tid + 224]; }
    if (tid < 7)   { as2s[tid] = a_src2[tid]; ad2s[tid] = a_dst2[tid]; }
    __syncthreads();

    int d    = (blockIdx.x * blockDim.x + tid) >> 5;
    int lane = tid & 31;
    if (d >= N_NODES) return;

    float ad_d = g_ad[d];
    int j = g_off[d], end = g_off[d + 1];
    float den = 0.f, a0 = 0.f, a1 = 0.f;

    for (; j + 3 < end; j += 4) {
        int2 e0 = g_es[j],     e1 = g_es[j + 1];
        int2 e2 = g_es[j + 2], e3 = g_es[j + 3];
        float sa0 = g_as[e0.x], sa1 = g_as[e1.x];
        float sa2 = g_as[e2.x], sa3 = g_as[e3.x];
        __half2 h0 = g_h1h[e0.x * 32 + lane];
        __half2 h1 = g_h1h[e1.x * 32 + lane];
        __half2 h2 = g_h1h[e2.x * 32 + lane];
        __half2 h3 = g_h1h[e3.x * 32 + lane];
        float x0 = sa0 + ad_d; x0 = (x0 > 0.f) ? x0 : NEG_SLOPE * x0;
        float x1 = sa1 + ad_d; x1 = (x1 > 0.f) ? x1 : NEG_SLOPE * x1;
        float x2 = sa2 + ad_d; x2 = (x2 > 0.f) ? x2 : NEG_SLOPE * x2;
        float x3 = sa3 + ad_d; x3 = (x3 > 0.f) ? x3 : NEG_SLOPE * x3;
        float ea0 = __expf(x0 + __int_as_float(e0.y));
        float ea1 = __expf(x1 + __int_as_float(e1.y));
        float ea2 = __expf(x2 + __int_as_float(e2.y));
        float ea3 = __expf(x3 + __int_as_float(e3.y));
        den += (ea0 + ea1) + (ea2 + ea3);
        float2 f0 = __half22float2(h0), f1 = __half22float2(h1);
        float2 f2 = __half22float2(h2), f3 = __half22float2(h3);
        a0 += ea0 * f0.x + ea1 * f1.x + ea2 * f2.x + ea3 * f3.x;
        a1 += ea0 * f0.y + ea1 * f1.y + ea2 * f2.y + ea3 * f3.y;
    }
    for (; j < end; ++j) {
        int2 e0 = g_es[j];
        float sa0 = g_as[e0.x];
        __half2 h0 = g_h1h[e0.x * 32 + lane];
        float x0 = sa0 + ad_d; x0 = (x0 > 0.f) ? x0 : NEG_SLOPE * x0;
        float ea0 = __expf(x0 + __int_as_float(e0.y));
        float2 f0 = __half22float2(h0);
        den += ea0;
        a0 += ea0 * f0.x;
        a1 += ea0 * f0.y;
    }

    float inv = 1.f / (den + EPS);
    float f0 = fmaxf(fmaf(a0, inv, b1[lane * 2]),     0.f);
    float f1 = fmaxf(fmaf(a1, inv, b1[lane * 2 + 1]), 0.f);

    float p[7];
#pragma unroll
    for (int c = 0; c < 7; ++c)
        p[c] = f0 * w2s[(lane * 2) * 7 + c] + f1 * w2s[(lane * 2 + 1) * 7 + c];
#pragma unroll
    for (int off = 16; off > 0; off >>= 1)
#pragma unroll
        for (int c = 0; c < 7; ++c)
            p[c] += __shfl_xor_sync(0xffffffffu, p[c], off);

    if (lane == 0) {
        float4 v0 = make_float4(p[0], p[1], p[2], p[3]);
        float4 v1 = make_float4(p[4], p[5], p[6], 0.f);
        *(float4*)&g_h2[d * 8]     = v0;
        *(float4*)&g_h2[d * 8 + 4] = v1;
        float s2 = 0.f, t2 = 0.f;
#pragma unroll
        for (int c = 0; c < 7; ++c) {
            s2 += p[c] * as2s[c];
            t2 += p[c] * ad2s[c];
        }
        g_as2[d] = s2;
        g_ad2[d] = t2;
    }
}

// ---------------- K3: fused layer-2 softmax+aggregate (8 lanes / dst) -------
__global__ void agg2_csr_kernel(float* __restrict__ out,
                                const float* __restrict__ b2) {
    int gt = blockIdx.x * blockDim.x + threadIdx.x;
    int d  = gt >> 3;
    int c  = gt & 7;
    if (d >= N_NODES) return;

    float ad_d = g_ad2[d];
    int j = g_off[d], end = g_off[d + 1];
    float den = 0.f, acc = 0.f;
    for (; j + 1 < end; j += 2) {
        int2 e0 = g_es[j], e1 = g_es[j + 1];
        float v0 = g_h2[e0.x * 8 + c];
        float v1 = g_h2[e1.x * 8 + c];
        float a0 = g_as2[e0.x] + ad_d; a0 = (a0 > 0.f) ? a0 : NEG_SLOPE * a0;
        float a1 = g_as2[e1.x] + ad_d; a1 = (a1 > 0.f) ? a1 : NEG_SLOPE * a1;
        float ea0 = __expf(a0 + __int_as_float(e0.y));
        float ea1 = __expf(a1 + __int_as_float(e1.y));
        den += ea0 + ea1;
        acc += ea0 * v0 + ea1 * v1;
    }
    if (j < end) {
        int2 e0 = g_es[j];
        float a0 = g_as2[e0.x] + ad_d; a0 = (a0 > 0.f) ? a0 : NEG_SLOPE * a0;
        float ea0 = __expf(a0 + __int_as_float(e0.y));
        den += ea0;
        acc += ea0 * g_h2[e0.x * 8 + c];
    }
    if (c < 7)
        out[d * 7 + c] = fmaf(acc, 1.f / (den + EPS), b2[c]);
}

// ---------------- launch (fork-join: CSR build overlaps gemm1) -------------
extern "C" void kernel_launch(void* const* d_in, const int* in_sizes, int n_in,
                              void* d_out, int out_size) {
    const float* x      = (const float*)d_in[0];
    const int*   ei     = (const int*)  d_in[1];
    const float* ew     = (const float*)d_in[2];
    const float* W1     = (const float*)d_in[3];
    const float* a_src1 = (const float*)d_in[4];
    const float* a_dst1 = (const float*)d_in[5];
    const float* b1     = (const float*)d_in[6];
    const float* W2     = (const float*)d_in[7];
    const float* a_src2 = (const float*)d_in[8];
    const float* a_dst2 = (const float*)d_in[9];
    const float* b2     = (const float*)d_in[10];
    float* out = (float*)d_out;

    // one-time resources (no device memory involved)
    static cudaStream_t s_side = nullptr;
    static cudaEvent_t ev_fork = nullptr, ev_join = nullptr;
    if (!s_side) {
        cudaStreamCreateWithFlags(&s_side, cudaStreamNonBlocking);
        cudaEventCreateWithFlags(&ev_fork, cudaEventDisableTiming);
        cudaEventCreateWithFlags(&ev_join, cudaEventDisableTiming);
    }

    // fork: CSR build chain on side stream
    cudaEventRecord(ev_fork, 0);
    cudaStreamWaitEvent(s_side, ev_fork, 0);
    zero_deg_kernel<<<(N_NODES + 255) / 256, 256, 0, s_side>>>();
    hist_kernel<<<(N_TOT + 255) / 256, 256, 0, s_side>>>(ei);
    scanA_kernel<<<NSCAN, 256, 0, s_side>>>();
    scanC_kernel<<<(N_NODES + 255) / 256, 256, 0, s_side>>>();
    scatter_kernel<<<(N_TOT + 255) / 256, 256, 0, s_side>>>(ei, ew);
    cudaEventRecord(ev_join, s_side);

    // main stream: GEMM1 + fused alphas (independent of CSR build)
    gemm1_kernel<<<(N_NODES + 63) / 64, 256>>>(x, W1, a_src1, a_dst1);

    // join, then fused aggregations
    cudaStreamWaitEvent(0, ev_join, 0);
    agg1_csr_kernel<<<(N_NODES * 32 + 255) / 256, 256>>>(b1, W2, a_src2, a_dst2);
    agg2_csr_kernel<<<(N_NODES * 8 + 255) / 256, 256>>>(out, b2);
}

// round 5
// speedup vs baseline: 1.8590x; 1.0650x over previous
#include <cuda_runtime.h>
#include <cuda_fp16.h>
#include <cstdint>

#define N_NODES 100000
#define N_EDGES 1600000
#define N_TOT   1700000           // edges + self loops
#define NEG_SLOPE 0.2f
#define EPS 1e-16f
#define SCAN_B 1024
#define NSCAN ((N_NODES + SCAN_B - 1) / SCAN_B)   // 98

// ---------------- scratch (device globals; no allocation allowed) ----------
__device__ __half2 g_h1h[N_NODES * 32];  // layer-1 features (fp16, gather-only)
__device__ float g_h2[N_NODES * 8];      // layer-2 features (padded 7->8)
__device__ float g_as[N_NODES];          // layer-1 alpha_src per node
__device__ float g_ad[N_NODES];          // layer-1 alpha_dst per node
__device__ float g_as2[N_NODES];         // layer-2 alpha_src per node
__device__ float g_ad2[N_NODES];         // layer-2 alpha_dst per node
__device__ int   g_deg[N_NODES];         // in-degree histogram
__device__ int   g_off[N_NODES + 1];     // CSR row offsets (by dst)
__device__ int   g_cur[N_NODES];         // scatter cursors
__device__ int   g_bsum[NSCAN];          // scan block sums
__device__ int2  g_es[N_TOT];            // CSR payload: (src, adj bits)

// ---------------- tf32 helpers ---------------------------------------------
__device__ __forceinline__ uint32_t f2tf32(float f) {
    uint32_t r;
    asm("cvt.rna.tf32.f32 %0, %1;" : "=r"(r) : "f"(f));
    return r;
}

__device__ __forceinline__ void mma16n8k8(float* d,
                                          uint32_t a0, uint32_t a1,
                                          uint32_t a2, uint32_t a3,
                                          uint32_t b0, uint32_t b1) {
    asm volatile(
        "mma.sync.aligned.m16n8k8.row.col.f32.tf32.tf32.f32 "
        "{%0,%1,%2,%3}, {%4,%5,%6,%7}, {%8,%9}, {%0,%1,%2,%3};"
        : "+f"(d[0]), "+f"(d[1]), "+f"(d[2]), "+f"(d[3])
        : "r"(a0), "r"(a1), "r"(a2), "r"(a3), "r"(b0), "r"(b1));
}

// ---------------- K1: h1 = x @ W1 via 3xTF32 mma, fused alphas -------------
// Block: 256 threads (8 warps), tile 128 rows x 64 cols, full K=128 staged.
__global__ __launch_bounds__(256, 2)
void gemm1_mma_kernel(const float* __restrict__ x,
                      const float* __restrict__ W1,
                      const float* __restrict__ a_src,
                      const float* __restrict__ a_dst) {
    extern __shared__ float smem[];
    float* As = smem;              // 128 x 128, XOR-swizzled
    float* Bs = smem + 128 * 128;  // 128 x 64, XOR-swizzled
    __shared__ float as_s[64], ad_s[64];

    const int t = threadIdx.x;
    const int rbase = blockIdx.x * 128;

    // stage x tile (zeros beyond N_NODES)
#pragma unroll
    for (int i = 0; i < 16; ++i) {
        int fid = i * 256 + t;          // 4096 float4
        int row = fid >> 5;
        int k4  = (fid & 31) * 4;
        int gr  = rbase + row;
        float4 v = make_float4(0.f, 0.f, 0.f, 0.f);
        if (gr < N_NODES) v = *(const float4*)&x[gr * 128 + k4];
        int ks = k4 ^ ((row & 7) << 2);
        *(float4*)&As[row * 128 + ks] = v;
    }
    // stage W1
#pragma unroll
    for (int i = 0; i < 8; ++i) {
        int fid = i * 256 + t;          // 2048 float4
        int k  = fid >> 4;
        int n4 = (fid & 15) * 4;
        float4 v = *(const float4*)&W1[k * 64 + n4];
        int ns = n4 ^ ((k & 3) << 3);
        *(float4*)&Bs[k * 64 + ns] = v;
    }
    if (t < 64)       as_s[t]      = a_src[t];
    else if (t < 128) ad_s[t - 64] = a_dst[t - 64];
    __syncthreads();

    const int w    = t >> 5;
    const int lane = t & 31;
    const int g    = lane >> 2;
    const int tg   = lane & 3;
    const int wr   = w * 16;

    float acc[8][4];
#pragma unroll
    for (int i = 0; i < 8; ++i)
#pragma unroll
        for (int j = 0; j < 4; ++j) acc[i][j] = 0.f;

    const int aOff0 = (wr + g) * 128;
    const int aOff1 = aOff0 + 8 * 128;
    const int sA    = g << 2;

#pragma unroll
    for (int step = 0; step < 16; ++step) {
        const int kb  = step * 8;
        const int ia0 = (kb + tg) ^ sA;
        float af0 = As[aOff0 + ia0];
        float af1 = As[aOff1 + ia0];
        float af2 = As[aOff0 + (ia0 ^ 4)];
        float af3 = As[aOff1 + (ia0 ^ 4)];
        uint32_t ah0 = f2tf32(af0), ah1 = f2tf32(af1);
        uint32_t ah2 = f2tf32(af2), ah3 = f2tf32(af3);
        uint32_t al0 = f2tf32(af0 - __uint_as_float(ah0));
        uint32_t al1 = f2tf32(af1 - __uint_as_float(ah1));
        uint32_t al2 = f2tf32(af2 - __uint_as_float(ah2));
        uint32_t al3 = f2tf32(af3 - __uint_as_float(ah3));
        const int bRow = (kb + tg) * 64 + g;
#pragma unroll
        for (int nt = 0; nt < 8; ++nt) {
            int bi0 = bRow + ((nt ^ tg) << 3);
            float bf0 = Bs[bi0];
            float bf1 = Bs[bi0 + 256];     // k+4 row
            uint32_t bh0 = f2tf32(bf0), bh1 = f2tf32(bf1);
            uint32_t bl0 = f2tf32(bf0 - __uint_as_float(bh0));
            uint32_t bl1 = f2tf32(bf1 - __uint_as_float(bh1));
            mma16n8k8(acc[nt], ah0, ah1, ah2, ah3, bh0, bh1);
            mma16n8k8(acc[nt], al0, al1, al2, al3, bh0, bh1);
            mma16n8k8(acc[nt], ah0, ah1, ah2, ah3, bl0, bl1);
        }
    }

    // epilogue: fp16 h1 store + fused alpha dot products
    const int r0 = rbase + wr + g;
    const int r1 = r0 + 8;
    float pas0 = 0.f, pad0 = 0.f, pas1 = 0.f, pad1 = 0.f;
#pragma unroll
    for (int nt = 0; nt < 8; ++nt) {
        int c = nt * 8 + 2 * tg;
        float2 av = *(const float2*)&as_s[c];
        float2 dv = *(const float2*)&ad_s[c];
        pas0 += acc[nt][0] * av.x + acc[nt][1] * av.y;
        pad0 += acc[nt][0] * dv.x + acc[nt][1] * dv.y;
        pas1 += acc[nt][2] * av.x + acc[nt][3] * av.y;
        pad1 += acc[nt][2] * dv.x + acc[nt][3] * dv.y;
        if (r0 < N_NODES)
            g_h1h[r0 * 32 + nt * 4 + tg] = __floats2half2_rn(acc[nt][0], acc[nt][1]);
        if (r1 < N_NODES)
            g_h1h[r1 * 32 + nt * 4 + tg] = __floats2half2_rn(acc[nt][2], acc[nt][3]);
    }
#pragma unroll
    for (int off = 1; off <= 2; off <<= 1) {
        pas0 += __shfl_xor_sync(0xffffffffu, pas0, off);
        pad0 += __shfl_xor_sync(0xffffffffu, pad0, off);
        pas1 += __shfl_xor_sync(0xffffffffu, pas1, off);
        pad1 += __shfl_xor_sync(0xffffffffu, pad1, off);
    }
    if (tg == 0) {
        if (r0 < N_NODES) { g_as[r0] = pas0; g_ad[r0] = pad0; }
        if (r1 < N_NODES) { g_as[r1] = pas1; g_ad[r1] = pad1; }
    }
}

// ---------------- CSR build (side stream, overlapped with gemm1) -----------
__global__ void zero_deg_kernel() {
    int i = blockIdx.x * blockDim.x + threadIdx.x;
    if (i < N_NODES) g_deg[i] = 0;
}

__global__ void hist_kernel(const int* __restrict__ ei) {
    int e = blockIdx.x * blockDim.x + threadIdx.x;
    if (e >= N_TOT) return;
    int d = (e < N_EDGES) ? ei[N_EDGES + e] : (e - N_EDGES);
    atomicAdd(&g_deg[d], 1);
}

__global__ void scanA_kernel() {
    __shared__ int sh[256];
    int tid  = threadIdx.x;
    int base = blockIdx.x * SCAN_B + tid * 4;
    int v[4];
#pragma unroll
    for (int k = 0; k < 4; ++k)
        v[k] = (base + k < N_NODES) ? g_deg[base + k] : 0;
    int local = v[0] + v[1] + v[2] + v[3];
    sh[tid] = local;
    __syncthreads();
    for (int off = 1; off < 256; off <<= 1) {
        int t2 = (tid >= off) ? sh[tid - off] : 0;
        __syncthreads();
        sh[tid] += t2;
        __syncthreads();
    }
    int incl = sh[tid];
    if (tid == 255) g_bsum[blockIdx.x] = incl;
    int run = incl - local;
#pragma unroll
    for (int k = 0; k < 4; ++k) {
        if (base + k < N_NODES) g_off[base + k] = run;
        run += v[k];
    }
}

// scanC folds the (tiny) 98-entry block-sum scan in redundantly per block.
__global__ void scanC_kernel() {
    __shared__ int sh[128];
    __shared__ int orig[128];
    int tid = threadIdx.x;
    if (tid < 128) {
        int v = (tid < NSCAN) ? g_bsum[tid] : 0;
        orig[tid] = v;
        sh[tid] = v;
    }
    __syncthreads();
    for (int off = 1; off < 128; off <<= 1) {
        int t2 = (tid >= off && tid < 128) ? sh[tid - off] : 0;
        __syncthreads();
        if (tid < 128) sh[tid] += t2;
        __syncthreads();
    }
    int i = blockIdx.x * blockDim.x + tid;
    if (i < N_NODES) {
        int blk = i >> 10;
        int o = g_off[i] + (sh[blk] - orig[blk]);   // + exclusive block prefix
        g_off[i] = o;
        g_cur[i] = o;
    }
    if (i == 0) g_off[N_NODES] = N_TOT;
}

__global__ void scatter_kernel(const int* __restrict__ ei,
                               const float* __restrict__ ew) {
    int e = blockIdx.x * blockDim.x + threadIdx.x;
    if (e >= N_TOT) return;
    int s, d; float adj;
    if (e < N_EDGES) {
        s = ei[e]; d = ei[N_EDGES + e];
        adj = 1.f - 1.f / ew[e];
    } else {
        s = d = e - N_EDGES;
        adj = 0.f;
    }
    int pos = atomicAdd(&g_cur[d], 1);
    g_es[pos] = make_int2(s, __float_as_int(adj));
}

// ---------------- K2: fused layer-1 softmax+aggregate + layer-2 features ----
__global__ void agg1_csr_kernel(const float* __restrict__ b1,
                                const float* __restrict__ W2,
                                const float* __restrict__ a_src2,
                                const float* __restrict__ a_dst2) {
    __shared__ float w2s[448];
    __shared__ float as2s[8], ad2s[8];
    int tid = threadIdx.x;
    if (tid < 224) { w2s[tid] = W2[tid]; w2s[tid + 224] = W2[tid + 224]; }
    if (tid < 7)   { as2s[tid] = a_src2[tid]; ad2s[tid] = a_dst2[tid]; }
    __syncthreads();

    int d    = (blockIdx.x * blockDim.x + tid) >> 5;
    int lane = tid & 31;
    if (d >= N_NODES) return;

    float ad_d = g_ad[d];
    int j = g_off[d], end = g_off[d + 1];
    float den = 0.f, a0 = 0.f, a1 = 0.f;

    for (; j + 3 < end; j += 4) {
        int2 e0 = g_es[j],     e1 = g_es[j + 1];
        int2 e2 = g_es[j + 2], e3 = g_es[j + 3];
        float sa0 = g_as[e0.x], sa1 = g_as[e1.x];
        float sa2 = g_as[e2.x], sa3 = g_as[e3.x];
        __half2 h0 = g_h1h[e0.x * 32 + lane];
        __half2 h1 = g_h1h[e1.x * 32 + lane];
        __half2 h2 = g_h1h[e2.x * 32 + lane];
        __half2 h3 = g_h1h[e3.x * 32 + lane];
        float x0 = sa0 + ad_d; x0 = (x0 > 0.f) ? x0 : NEG_SLOPE * x0;
        float x1 = sa1 + ad_d; x1 = (x1 > 0.f) ? x1 : NEG_SLOPE * x1;
        float x2 = sa2 + ad_d; x2 = (x2 > 0.f) ? x2 : NEG_SLOPE * x2;
        float x3 = sa3 + ad_d; x3 = (x3 > 0.f) ? x3 : NEG_SLOPE * x3;
        float ea0 = __expf(x0 + __int_as_float(e0.y));
        float ea1 = __expf(x1 + __int_as_float(e1.y));
        float ea2 = __expf(x2 + __int_as_float(e2.y));
        float ea3 = __expf(x3 + __int_as_float(e3.y));
        den += (ea0 + ea1) + (ea2 + ea3);
        float2 f0 = __half22float2(h0), f1 = __half22float2(h1);
        float2 f2 = __half22float2(h2), f3 = __half22float2(h3);
        a0 += ea0 * f0.x + ea1 * f1.x + ea2 * f2.x + ea3 * f3.x;
        a1 += ea0 * f0.y + ea1 * f1.y + ea2 * f2.y + ea3 * f3.y;
    }
    for (; j < end; ++j) {
        int2 e0 = g_es[j];
        float sa0 = g_as[e0.x];
        __half2 h0 = g_h1h[e0.x * 32 + lane];
        float x0 = sa0 + ad_d; x0 = (x0 > 0.f) ? x0 : NEG_SLOPE * x0;
        float ea0 = __expf(x0 + __int_as_float(e0.y));
        float2 f0 = __half22float2(h0);
        den += ea0;
        a0 += ea0 * f0.x;
        a1 += ea0 * f0.y;
    }

    float inv = 1.f / (den + EPS);
    float f0 = fmaxf(fmaf(a0, inv, b1[lane * 2]),     0.f);
    float f1 = fmaxf(fmaf(a1, inv, b1[lane * 2 + 1]), 0.f);

    float p[7];
#pragma unroll
    for (int c = 0; c < 7; ++c)
        p[c] = f0 * w2s[(lane * 2) * 7 + c] + f1 * w2s[(lane * 2 + 1) * 7 + c];
#pragma unroll
    for (int off = 16; off > 0; off >>= 1)
#pragma unroll
        for (int c = 0; c < 7; ++c)
            p[c] += __shfl_xor_sync(0xffffffffu, p[c], off);

    if (lane == 0) {
        float4 v0 = make_float4(p[0], p[1], p[2], p[3]);
        float4 v1 = make_float4(p[4], p[5], p[6], 0.f);
        *(float4*)&g_h2[d * 8]     = v0;
        *(float4*)&g_h2[d * 8 + 4] = v1;
        float s2 = 0.f, t2 = 0.f;
#pragma unroll
        for (int c = 0; c < 7; ++c) {
            s2 += p[c] * as2s[c];
            t2 += p[c] * ad2s[c];
        }
        g_as2[d] = s2;
        g_ad2[d] = t2;
    }
}

// ---------------- K3: fused layer-2 softmax+aggregate (8 lanes / dst) -------
__global__ void agg2_csr_kernel(float* __restrict__ out,
                                const float* __restrict__ b2) {
    int gt = blockIdx.x * blockDim.x + threadIdx.x;
    int d  = gt >> 3;
    int c  = gt & 7;
    if (d >= N_NODES) return;

    float ad_d = g_ad2[d];
    int j = g_off[d], end = g_off[d + 1];
    float den = 0.f, acc = 0.f;
    for (; j + 1 < end; j += 2) {
        int2 e0 = g_es[j], e1 = g_es[j + 1];
        float v0 = g_h2[e0.x * 8 + c];
        float v1 = g_h2[e1.x * 8 + c];
        float a0 = g_as2[e0.x] + ad_d; a0 = (a0 > 0.f) ? a0 : NEG_SLOPE * a0;
        float a1 = g_as2[e1.x] + ad_d; a1 = (a1 > 0.f) ? a1 : NEG_SLOPE * a1;
        float ea0 = __expf(a0 + __int_as_float(e0.y));
        float ea1 = __expf(a1 + __int_as_float(e1.y));
        den += ea0 + ea1;
        acc += ea0 * v0 + ea1 * v1;
    }
    if (j < end) {
        int2 e0 = g_es[j];
        float a0 = g_as2[e0.x] + ad_d; a0 = (a0 > 0.f) ? a0 : NEG_SLOPE * a0;
        float ea0 = __expf(a0 + __int_as_float(e0.y));
        den += ea0;
        acc += ea0 * g_h2[e0.x * 8 + c];
    }
    if (c < 7)
        out[d * 7 + c] = fmaf(acc, 1.f / (den + EPS), b2[c]);
}

// ---------------- launch (fork-join: CSR build overlaps gemm1) -------------
extern "C" void kernel_launch(void* const* d_in, const int* in_sizes, int n_in,
                              void* d_out, int out_size) {
    const float* x      = (const float*)d_in[0];
    const int*   ei     = (const int*)  d_in[1];
    const float* ew     = (const float*)d_in[2];
    const float* W1     = (const float*)d_in[3];
    const float* a_src1 = (const float*)d_in[4];
    const float* a_dst1 = (const float*)d_in[5];
    const float* b1     = (const float*)d_in[6];
    const float* W2     = (const float*)d_in[7];
    const float* a_src2 = (const float*)d_in[8];
    const float* a_dst2 = (const float*)d_in[9];
    const float* b2     = (const float*)d_in[10];
    float* out = (float*)d_out;

    const int GEMM_SMEM = (128 * 128 + 128 * 64) * 4;   // 96 KB

    // one-time resources (no device memory involved)
    static cudaStream_t s_side = nullptr;
    static cudaEvent_t ev_fork = nullptr, ev_join = nullptr;
    if (!s_side) {
        cudaStreamCreateWithFlags(&s_side, cudaStreamNonBlocking);
        cudaEventCreateWithFlags(&ev_fork, cudaEventDisableTiming);
        cudaEventCreateWithFlags(&ev_join, cudaEventDisableTiming);
        cudaFuncSetAttribute(gemm1_mma_kernel,
                             cudaFuncAttributeMaxDynamicSharedMemorySize,
                             GEMM_SMEM);
    }

    // fork: CSR build chain on side stream
    cudaEventRecord(ev_fork, 0);
    cudaStreamWaitEvent(s_side, ev_fork, 0);
    zero_deg_kernel<<<(N_NODES + 255) / 256, 256, 0, s_side>>>();
    hist_kernel<<<(N_TOT + 255) / 256, 256, 0, s_side>>>(ei);
    scanA_kernel<<<NSCAN, 256, 0, s_side>>>();
    scanC_kernel<<<(N_NODES + 255) / 256, 256, 0, s_side>>>();
    scatter_kernel<<<(N_TOT + 255) / 256, 256, 0, s_side>>>(ei, ew);
    cudaEventRecord(ev_join, s_side);

    // main stream: GEMM1 via 3xTF32 mma (independent of CSR build)
    gemm1_mma_kernel<<<(N_NODES + 127) / 128, 256, GEMM_SMEM>>>(
        x, W1, a_src1, a_dst1);

    // join, then fused aggregations
    cudaStreamWaitEvent(0, ev_join, 0);
    agg1_csr_kernel<<<(N_NODES * 32 + 255) / 256, 256>>>(b1, W2, a_src2, a_dst2);
    agg2_csr_kernel<<<(N_NODES * 8 + 255) / 256, 256>>>(out, b2);
}

// round 7
// speedup vs baseline: 1.8979x; 1.0210x over previous
#include <cuda_runtime.h>
#include <cuda_fp16.h>
#include <cstdint>

#define N_NODES 100000
#define N_EDGES 1600000
#define N_TOT   1700000           // edges + self loops
#define NEG_SLOPE 0.2f
#define EPS 1e-16f
#define SCAN_B 1024
#define NSCAN ((N_NODES + SCAN_B - 1) / SCAN_B)   // 98

// ---------------- scratch (device globals; no allocation allowed) ----------
__device__ __half2 g_h1h[N_NODES * 32];  // layer-1 features (fp16, gather-only)
__device__ float g_h2[N_NODES * 8];      // layer-2 features (padded 7->8)
__device__ float g_as[N_NODES];          // layer-1 alpha_src per node
__device__ float g_ad[N_NODES];          // layer-1 alpha_dst per node
__device__ float g_as2[N_NODES];         // layer-2 alpha_src per node
__device__ float g_ad2[N_NODES];         // layer-2 alpha_dst per node
__device__ int   g_deg[N_NODES];         // in-degree histogram (zeroed by scan)
__device__ int   g_off[N_NODES + 1];     // CSR row offsets (by dst)
__device__ int   g_cur[N_NODES];         // scatter cursors
__device__ int   g_bsum[NSCAN];          // scan block sums
__device__ int   g_arrive;               // grid-barrier counters (self-reset)
__device__ int   g_depart;
__device__ int2  g_es[N_TOT];            // CSR payload: (src, adj bits)

// ---------------- tf32 helpers ---------------------------------------------
__device__ __forceinline__ uint32_t f2tf32(float f) {
    uint32_t r;
    asm("cvt.rna.tf32.f32 %0, %1;" : "=r"(r) : "f"(f));
    return r;
}

__device__ __forceinline__ void mma16n8k8(float* d,
                                          uint32_t a0, uint32_t a1,
                                          uint32_t a2, uint32_t a3,
                                          uint32_t b0, uint32_t b1) {
    asm volatile(
        "mma.sync.aligned.m16n8k8.row.col.f32.tf32.tf32.f32 "
        "{%0,%1,%2,%3}, {%4,%5,%6,%7}, {%8,%9}, {%0,%1,%2,%3};"
        : "+f"(d[0]), "+f"(d[1]), "+f"(d[2]), "+f"(d[3])
        : "r"(a0), "r"(a1), "r"(a2), "r"(a3), "r"(b0), "r"(b1));
}

// ---------------- K1: h1 = x @ W1 via 3xTF32 mma, fused alphas -------------
__global__ __launch_bounds__(256, 2)
void gemm1_mma_kernel(const float* __restrict__ x,
                      const float* __restrict__ W1,
                      const float* __restrict__ a_src,
                      const float* __restrict__ a_dst) {
    extern __shared__ float smem[];
    float* As = smem;              // 128 x 128, XOR-swizzled
    float* Bs = smem + 128 * 128;  // 128 x 64, XOR-swizzled
    __shared__ float as_s[64], ad_s[64];

    const int t = threadIdx.x;
    const int rbase = blockIdx.x * 128;

#pragma unroll
    for (int i = 0; i < 16; ++i) {
        int fid = i * 256 + t;
        int row = fid >> 5;
        int k4  = (fid & 31) * 4;
        int gr  = rbase + row;
        float4 v = make_float4(0.f, 0.f, 0.f, 0.f);
        if (gr < N_NODES) v = *(const float4*)&x[gr * 128 + k4];
        int ks = k4 ^ ((row & 7) << 2);
        *(float4*)&As[row * 128 + ks] = v;
    }
#pragma unroll
    for (int i = 0; i < 8; ++i) {
        int fid = i * 256 + t;
        int k  = fid >> 4;
        int n4 = (fid & 15) * 4;
        float4 v = *(const float4*)&W1[k * 64 + n4];
        int ns = n4 ^ ((k & 3) << 3);
        *(float4*)&Bs[k * 64 + ns] = v;
    }
    if (t < 64)       as_s[t]      = a_src[t];
    else if (t < 128) ad_s[t - 64] = a_dst[t - 64];
    __syncthreads();

    const int w    = t >> 5;
    const int lane = t & 31;
    const int g    = lane >> 2;
    const int tg   = lane & 3;
    const int wr   = w * 16;

    float acc[8][4];
#pragma unroll
    for (int i = 0; i < 8; ++i)
#pragma unroll
        for (int j = 0; j < 4; ++j) acc[i][j] = 0.f;

    const int aOff0 = (wr + g) * 128;
    const int aOff1 = aOff0 + 8 * 128;
    const int sA    = g << 2;

#pragma unroll
    for (int step = 0; step < 16; ++step) {
        const int kb  = step * 8;
        const int ia0 = (kb + tg) ^ sA;
        float af0 = As[aOff0 + ia0];
        float af1 = As[aOff1 + ia0];
        float af2 = As[aOff0 + (ia0 ^ 4)];
        float af3 = As[aOff1 + (ia0 ^ 4)];
        uint32_t ah0 = f2tf32(af0), ah1 = f2tf32(af1);
        uint32_t ah2 = f2tf32(af2), ah3 = f2tf32(af3);
        uint32_t al0 = f2tf32(af0 - __uint_as_float(ah0));
        uint32_t al1 = f2tf32(af1 - __uint_as_float(ah1));
        uint32_t al2 = f2tf32(af2 - __uint_as_float(ah2));
        uint32_t al3 = f2tf32(af3 - __uint_as_float(ah3));
        const int bRow = (kb + tg) * 64 + g;
#pragma unroll
        for (int nt = 0; nt < 8; ++nt) {
            int bi0 = bRow + ((nt ^ tg) << 3);
            float bf0 = Bs[bi0];
            float bf1 = Bs[bi0 + 256];
            uint32_t bh0 = f2tf32(bf0), bh1 = f2tf32(bf1);
            uint32_t bl0 = f2tf32(bf0 - __uint_as_float(bh0));
            uint32_t bl1 = f2tf32(bf1 - __uint_as_float(bh1));
            mma16n8k8(acc[nt], ah0, ah1, ah2, ah3, bh0, bh1);
            mma16n8k8(acc[nt], al0, al1, al2, al3, bh0, bh1);
            mma16n8k8(acc[nt], ah0, ah1, ah2, ah3, bl0, bl1);
        }
    }

    const int r0 = rbase + wr + g;
    const int r1 = r0 + 8;
    float pas0 = 0.f, pad0 = 0.f, pas1 = 0.f, pad1 = 0.f;
#pragma unroll
    for (int nt = 0; nt < 8; ++nt) {
        int c = nt * 8 + 2 * tg;
        float2 av = *(const float2*)&as_s[c];
        float2 dv = *(const float2*)&ad_s[c];
        pas0 += acc[nt][0] * av.x + acc[nt][1] * av.y;
        pad0 += acc[nt][0] * dv.x + acc[nt][1] * dv.y;
        pas1 += acc[nt][2] * av.x + acc[nt][3] * av.y;
        pad1 += acc[nt][2] * dv.x + acc[nt][3] * dv.y;
        if (r0 < N_NODES)
            g_h1h[r0 * 32 + nt * 4 + tg] = __floats2half2_rn(acc[nt][0], acc[nt][1]);
        if (r1 < N_NODES)
            g_h1h[r1 * 32 + nt * 4 + tg] = __floats2half2_rn(acc[nt][2], acc[nt][3]);
    }
#pragma unroll
    for (int off = 1; off <= 2; off <<= 1) {
        pas0 += __shfl_xor_sync(0xffffffffu, pas0, off);
        pad0 += __shfl_xor_sync(0xffffffffu, pad0, off);
        pas1 += __shfl_xor_sync(0xffffffffu, pas1, off);
        pad1 += __shfl_xor_sync(0xffffffffu, pad1, off);
    }
    if (tg == 0) {
        if (r0 < N_NODES) { g_as[r0] = pas0; g_ad[r0] = pad0; }
        if (r1 < N_NODES) { g_as[r1] = pas1; g_ad[r1] = pad1; }
    }
}

// ---------------- CSR build (side stream, overlapped with gemm1) -----------
// hist: 4 edges per thread via int4 (g_deg pre-zeroed by previous call's scan
// or by static zero-init on the very first call).
__global__ void hist_kernel(const int* __restrict__ ei) {
    int t = blockIdx.x * blockDim.x + threadIdx.x;
    int e4 = t * 4;
    if (e4 + 3 < N_EDGES) {
        int4 d4 = *(const int4*)&ei[N_EDGES + e4];
        atomicAdd(&g_deg[d4.x], 1);
        atomicAdd(&g_deg[d4.y], 1);
        atomicAdd(&g_deg[d4.z], 1);
        atomicAdd(&g_deg[d4.w], 1);
    } else {
        for (int e = e4; e < N_EDGES && e < e4 + 4; ++e)
            atomicAdd(&g_deg[ei[N_EDGES + e]], 1);
    }
    // self loops: dst = node id, one increment each
    if (t < N_NODES) atomicAdd(&g_deg[t], 1);
}

// Fused scan: block-local scan + grid barrier + global prefix + cursor init
// + g_deg zeroing. 98 blocks, all resident -> spin barrier is safe.
// tid 0 publishes the block sum itself (writer == fencer == arriver).
__global__ void fused_scan_kernel() {
    __shared__ int sh[256];
    __shared__ int bs[NSCAN];
    const int tid = threadIdx.x;
    const int b   = blockIdx.x;
    const int base = b * SCAN_B + tid * 4;

    int v[4];
#pragma unroll
    for (int k = 0; k < 4; ++k)
        v[k] = (base + k < N_NODES) ? g_deg[base + k] : 0;
    int local = v[0] + v[1] + v[2] + v[3];
    sh[tid] = local;
    __syncthreads();
    for (int off = 1; off < 256; off <<= 1) {
        int t2 = (tid >= off) ? sh[tid - off] : 0;
        __syncthreads();
        sh[tid] += t2;
        __syncthreads();
    }
    int incl = sh[tid];

    // grid barrier (publish + arrive), all by tid 0
    if (tid == 0) {
        g_bsum[b] = sh[255];          // block total (valid after scan)
        __threadfence();
        atomicAdd(&g_arrive, 1);
        while (*(volatile int*)&g_arrive < NSCAN) { }
    }
    __syncthreads();

    // block prefix from all block sums
    if (tid < NSCAN) bs[tid] = *(volatile int*)&g_bsum[tid];
    __syncthreads();
    int bpre = 0;
    for (int i = 0; i < b; ++i) bpre += bs[i];

    int run = bpre + incl - local;
#pragma unroll
    for (int k = 0; k < 4; ++k) {
        if (base + k < N_NODES) {
            g_off[base + k] = run;
            g_cur[base + k] = run;
            g_deg[base + k] = 0;      // ready for next call
        }
        run += v[k];
    }
    if (b == NSCAN - 1 && tid == 255) g_off[N_NODES] = N_TOT;

    // grid barrier (depart + self-reset, deterministic: counters end at 0)
    __syncthreads();
    if (tid == 0) {
        int old = atomicAdd(&g_depart, 1);
        if (old == NSCAN - 1) { g_depart = 0; g_arrive = 0; }
    }
}

__global__ void scatter_kernel(const int* __restrict__ ei,
                               const float* __restrict__ ew) {
    int e = blockIdx.x * blockDim.x + threadIdx.x;
    if (e >= N_TOT) return;
    int s, d; float adj;
    if (e < N_EDGES) {
        s = ei[e]; d = ei[N_EDGES + e];
        adj = 1.f - 1.f / ew[e];
    } else {
        s = d = e - N_EDGES;
        adj = 0.f;
    }
    int pos = atomicAdd(&g_cur[d], 1);
    g_es[pos] = make_int2(s, __float_as_int(adj));
}

// ---------------- K2: fused layer-1 softmax+aggregate + layer-2 features ----
// One warp per dst node, 2 features per lane; 8-edge batches for MLP.
__global__ void agg1_csr_kernel(const float* __restrict__ b1,
                                const float* __restrict__ W2,
                                const float* __restrict__ a_src2,
                                const float* __restrict__ a_dst2) {
    __shared__ float w2s[448];
    __shared__ float as2s[8], ad2s[8];
    __shared__ float b1s[64];
    int tid = threadIdx.x;
    if (tid < 224) { w2s[tid] = W2[tid]; w2s[tid + 224] = W2[tid + 224]; }
    if (tid < 7)   { as2s[tid] = a_src2[tid]; ad2s[tid] = a_dst2[tid]; }
    if (tid < 64)  b1s[tid] = b1[tid];           // FIXED: full 64-entry bias
    __syncthreads();

    int d    = (blockIdx.x * blockDim.x + tid) >> 5;
    int lane = tid & 31;
    if (d >= N_NODES) return;

    float ad_d = g_ad[d];
    int j = g_off[d], end = g_off[d + 1];
    float den = 0.f, a0 = 0.f, a1 = 0.f;

    for (; j + 7 < end; j += 8) {
        int2 e[8];
#pragma unroll
        for (int q = 0; q < 8; ++q) e[q] = g_es[j + q];
        float sa[8]; __half2 hh[8];
#pragma unroll
        for (int q = 0; q < 8; ++q) {
            sa[q] = g_as[e[q].x];
            hh[q] = g_h1h[e[q].x * 32 + lane];
        }
#pragma unroll
        for (int q = 0; q < 8; ++q) {
            float xx = sa[q] + ad_d; xx = (xx > 0.f) ? xx : NEG_SLOPE * xx;
            float ea = __expf(xx + __int_as_float(e[q].y));
            float2 f = __half22float2(hh[q]);
            den += ea; a0 += ea * f.x; a1 += ea * f.y;
        }
    }
    if (j + 3 < end) {
        int2 e[4];
#pragma unroll
        for (int q = 0; q < 4; ++q) e[q] = g_es[j + q];
        float sa[4]; __half2 hh[4];
#pragma unroll
        for (int q = 0; q < 4; ++q) {
            sa[q] = g_as[e[q].x];
            hh[q] = g_h1h[e[q].x * 32 + lane];
        }
#pragma unroll
        for (int q = 0; q < 4; ++q) {
            float xx = sa[q] + ad_d; xx = (xx > 0.f) ? xx : NEG_SLOPE * xx;
            float ea = __expf(xx + __int_as_float(e[q].y));
            float2 f = __half22float2(hh[q]);
            den += ea; a0 += ea * f.x; a1 += ea * f.y;
        }
        j += 4;
    }
    for (; j < end; ++j) {
        int2 e0 = g_es[j];
        float sa0 = g_as[e0.x];
        __half2 h0 = g_h1h[e0.x * 32 + lane];
        float xx = sa0 + ad_d; xx = (xx > 0.f) ? xx : NEG_SLOPE * xx;
        float ea = __expf(xx + __int_as_float(e0.y));
        float2 f = __half22float2(h0);
        den += ea; a0 += ea * f.x; a1 += ea * f.y;
    }

    float inv = 1.f / (den + EPS);
    float f0 = fmaxf(fmaf(a0, inv, b1s[lane * 2]),     0.f);
    float f1 = fmaxf(fmaf(a1, inv, b1s[lane * 2 + 1]), 0.f);

    float p[7];
#pragma unroll
    for (int c = 0; c < 7; ++c)
        p[c] = f0 * w2s[(lane * 2) * 7 + c] + f1 * w2s[(lane * 2 + 1) * 7 + c];
#pragma unroll
    for (int off = 16; off > 0; off >>= 1)
#pragma unroll
        for (int c = 0; c < 7; ++c)
            p[c] += __shfl_xor_sync(0xffffffffu, p[c], off);

    if (lane == 0) {
        float4 v0 = make_float4(p[0], p[1], p[2], p[3]);
        float4 v1 = make_float4(p[4], p[5], p[6], 0.f);
        *(float4*)&g_h2[d * 8]     = v0;
        *(float4*)&g_h2[d * 8 + 4] = v1;
        float s2 = 0.f, t2 = 0.f;
#pragma unroll
        for (int c = 0; c < 7; ++c) {
            s2 += p[c] * as2s[c];
            t2 += p[c] * ad2s[c];
        }
        g_as2[d] = s2;
        g_ad2[d] = t2;
    }
}

// ---------------- K3: fused layer-2 softmax+aggregate (8 lanes / dst) -------
__global__ void agg2_csr_kernel(float* __restrict__ out,
                                const float* __restrict__ b2) {
    int gt = blockIdx.x * blockDim.x + threadIdx.x;
    int d  = gt >> 3;
    int c  = gt & 7;
    if (d >= N_NODES) return;

    float ad_d = g_ad2[d];
    int j = g_off[d], end = g_off[d + 1];
    float den = 0.f, acc = 0.f;
    for (; j + 3 < end; j += 4) {
        int2 e[4];
#pragma unroll
        for (int q = 0; q < 4; ++q) e[q] = g_es[j + q];
        float sa[4], hv[4];
#pragma unroll
        for (int q = 0; q < 4; ++q) {
            sa[q] = g_as2[e[q].x];
            hv[q] = g_h2[e[q].x * 8 + c];
        }
#pragma unroll
        for (int q = 0; q < 4; ++q) {
            float a = sa[q] + ad_d; a = (a > 0.f) ? a : NEG_SLOPE * a;
            float ea = __expf(a + __int_as_float(e[q].y));
            den += ea; acc += ea * hv[q];
        }
    }
    for (; j < end; ++j) {
        int2 e0 = g_es[j];
        float a = g_as2[e0.x] + ad_d; a = (a > 0.f) ? a : NEG_SLOPE * a;
        float ea = __expf(a + __int_as_float(e0.y));
        den += ea;
        acc += ea * g_h2[e0.x * 8 + c];
    }
    if (c < 7)
        out[d * 7 + c] = fmaf(acc, 1.f / (den + EPS), b2[c]);
}

// ---------------- launch (fork-join: CSR build overlaps gemm1) -------------
extern "C" void kernel_launch(void* const* d_in, const int* in_sizes, int n_in,
                              void* d_out, int out_size) {
    const float* x      = (const float*)d_in[0];
    const int*   ei     = (const int*)  d_in[1];
    const float* ew     = (const float*)d_in[2];
    const float* W1     = (const float*)d_in[3];
    const float* a_src1 = (const float*)d_in[4];
    const float* a_dst1 = (const float*)d_in[5];
    const float* b1     = (const float*)d_in[6];
    const float* W2     = (const float*)d_in[7];
    const float* a_src2 = (const float*)d_in[8];
    const float* a_dst2 = (const float*)d_in[9];
    const float* b2     = (const float*)d_in[10];
    float* out = (float*)d_out;

    const int GEMM_SMEM = (128 * 128 + 128 * 64) * 4;   // 96 KB

    static cudaStream_t s_side = nullptr;
    static cudaEvent_t ev_fork = nullptr, ev_join = nullptr;
    if (!s_side) {
        cudaStreamCreateWithFlags(&s_side, cudaStreamNonBlocking);
        cudaEventCreateWithFlags(&ev_fork, cudaEventDisableTiming);
        cudaEventCreateWithFlags(&ev_join, cudaEventDisableTiming);
        cudaFuncSetAttribute(gemm1_mma_kernel,
                             cudaFuncAttributeMaxDynamicSharedMemorySize,
                             GEMM_SMEM);
    }

    // fork: CSR build chain on side stream (hist -> scan -> scatter)
    cudaEventRecord(ev_fork, 0);
    cudaStreamWaitEvent(s_side, ev_fork, 0);
    hist_kernel<<<((N_EDGES + 3) / 4 + 255) / 256, 256, 0, s_side>>>(ei);
    fused_scan_kernel<<<NSCAN, 256, 0, s_side>>>();
    scatter_kernel<<<(N_TOT + 255) / 256, 256, 0, s_side>>>(ei, ew);
    cudaEventRecord(ev_join, s_side);

    // main stream: GEMM1 via 3xTF32 mma (independent of CSR build)
    gemm1_mma_kernel<<<(N_NODES + 127) / 128, 256, GEMM_SMEM>>>(
        x, W1, a_src1, a_dst1);

    // join, then fused aggregations
    cudaStreamWaitEvent(0, ev_join, 0);
    agg1_csr_kernel<<<(N_NODES * 32 + 255) / 256, 256>>>(b1, W2, a_src2, a_dst2);
    agg2_csr_kernel<<<(N_NODES * 8 + 255) / 256, 256>>>(out, b2);
}